// round 1
// baseline (speedup 1.0000x reference)
#include <cuda_runtime.h>

// ---------------------------------------------------------------------------
// Graph attention layer, fp32, f32x2-packed FMA GEMMs.
//   out = concat(attn_node [N,128], attn_edge [E,128])
// ---------------------------------------------------------------------------

#define D        128
#define NMAX     10000
#define TILE     64
#define XLD      388   // 384 + 4 pad (row stride of X tile, floats)
#define HLD      132   // 128 + 4 pad (row stride of H tile, floats)
#define NTHREADS 256
#define SMEM_BYTES ((TILE*XLD + TILE*HLD + 64*D) * 4)

// scratch (device globals: no allocation allowed in kernel_launch)
__device__ __align__(16) float g_num_src[NMAX * D];
__device__ __align__(16) float g_den_src[NMAX * D];
__device__ __align__(16) float g_num_tgt[NMAX * D];
__device__ __align__(16) float g_den_tgt[NMAX * D];
__device__ __align__(16) float g_wsrcT[D * D];
__device__ __align__(16) float g_wtgtT[D * D];

typedef unsigned long long u64_t;

__device__ __forceinline__ u64_t pack2(float x) {
    u64_t r; asm("mov.b64 %0,{%1,%1};" : "=l"(r) : "f"(x)); return r;
}
__device__ __forceinline__ void unpack2(u64_t v, float& lo, float& hi) {
    asm("mov.b64 {%0,%1},%2;" : "=f"(lo), "=f"(hi) : "l"(v));
}
__device__ __forceinline__ void fma2(u64_t& d, u64_t a, u64_t b) {
    asm("fma.rn.f32x2 %0,%1,%2,%0;" : "+l"(d) : "l"(a), "l"(b));
}
__device__ __forceinline__ float siluf(float x)  { return x / (1.f + __expf(-x)); }
__device__ __forceinline__ float sigmf(float x)  { return 1.f / (1.f + __expf(-x)); }
__device__ __forceinline__ void red4(float* a, float x, float y, float z, float w) {
    asm volatile("red.global.add.v4.f32 [%0],{%1,%2,%3,%4};"
                 :: "l"(a), "f"(x), "f"(y), "f"(z), "f"(w) : "memory");
}
__device__ __forceinline__ float f4get(const float4& v, int i) {
    switch (i) { case 0: return v.x; case 1: return v.y; case 2: return v.z; default: return v.w; }
}

// OUT[r][c] += sum_k X[r][k] * W[k][c]  for a 64x128 tile.
// Thread (ty,tx) owns rows r0=ty*4..+3, cols c0=tx*8..+7. acc packs col pairs.
__device__ __forceinline__ void gemm_tile(
    const float* __restrict__ Xsm, int xld,
    const float* __restrict__ gW,          // global weights [Ktot][128] row-major
    float* __restrict__ Wsm,               // smem staging [64][128]
    int Ktot, u64_t acc[4][4], int r0, int c0, int tid)
{
    for (int kb = 0; kb < Ktot; kb += 64) {
        __syncthreads();
        #pragma unroll
        for (int t = 0; t < 8; ++t) {
            int idx = tid + t * NTHREADS;        // 0..2047
            int row = idx >> 5;
            int col = (idx & 31) << 2;
            *(float4*)(Wsm + row * D + col) =
                *(const float4*)(gW + (size_t)(kb + row) * D + col);
        }
        __syncthreads();
        #pragma unroll 2
        for (int k = 0; k < 64; k += 4) {
            float4 xr0 = *(const float4*)(Xsm + (r0 + 0) * xld + kb + k);
            float4 xr1 = *(const float4*)(Xsm + (r0 + 1) * xld + kb + k);
            float4 xr2 = *(const float4*)(Xsm + (r0 + 2) * xld + kb + k);
            float4 xr3 = *(const float4*)(Xsm + (r0 + 3) * xld + kb + k);
            #pragma unroll
            for (int kk = 0; kk < 4; ++kk) {
                ulonglong2 wA = *(const ulonglong2*)(Wsm + (k + kk) * D + c0);
                ulonglong2 wB = *(const ulonglong2*)(Wsm + (k + kk) * D + c0 + 4);
                u64_t xa = pack2(f4get(xr0, kk));
                u64_t xb = pack2(f4get(xr1, kk));
                u64_t xc = pack2(f4get(xr2, kk));
                u64_t xd = pack2(f4get(xr3, kk));
                fma2(acc[0][0], xa, wA.x); fma2(acc[0][1], xa, wA.y);
                fma2(acc[0][2], xa, wB.x); fma2(acc[0][3], xa, wB.y);
                fma2(acc[1][0], xb, wA.x); fma2(acc[1][1], xb, wA.y);
                fma2(acc[1][2], xb, wB.x); fma2(acc[1][3], xb, wB.y);
                fma2(acc[2][0], xc, wA.x); fma2(acc[2][1], xc, wA.y);
                fma2(acc[2][2], xc, wB.x); fma2(acc[2][3], xc, wB.y);
                fma2(acc[3][0], xd, wA.x); fma2(acc[3][1], xd, wA.y);
                fma2(acc[3][2], xd, wB.x); fma2(acc[3][3], xd, wB.y);
            }
        }
    }
}

__device__ __forceinline__ void zero_acc(u64_t acc[4][4]) {
    #pragma unroll
    for (int i = 0; i < 4; ++i)
        #pragma unroll
        for (int p = 0; p < 4; ++p) acc[i][p] = 0ULL;
}

__device__ __forceinline__ void acc_to_f(u64_t acc[4][4], float a[4][8]) {
    #pragma unroll
    for (int i = 0; i < 4; ++i)
        #pragma unroll
        for (int p = 0; p < 4; ++p) unpack2(acc[i][p], a[i][2*p], a[i][2*p+1]);
}

// LayerNorm across the 128-col row that is distributed over 16 tx lanes.
__device__ __forceinline__ void layernorm_rows(float a[4][8],
    const float* __restrict__ g, const float* __restrict__ b, int c0)
{
    float4 g0 = *(const float4*)(g + c0), g1 = *(const float4*)(g + c0 + 4);
    float4 b0 = *(const float4*)(b + c0), b1 = *(const float4*)(b + c0 + 4);
    float gv[8] = {g0.x, g0.y, g0.z, g0.w, g1.x, g1.y, g1.z, g1.w};
    float bv[8] = {b0.x, b0.y, b0.z, b0.w, b1.x, b1.y, b1.z, b1.w};
    #pragma unroll
    for (int i = 0; i < 4; ++i) {
        float s = 0.f;
        #pragma unroll
        for (int j = 0; j < 8; ++j) s += a[i][j];
        #pragma unroll
        for (int m = 8; m >= 1; m >>= 1) s += __shfl_xor_sync(0xffffffffu, s, m, 16);
        float mean = s * 0.0078125f;
        float v = 0.f;
        #pragma unroll
        for (int j = 0; j < 8; ++j) { float d = a[i][j] - mean; v += d * d; }
        #pragma unroll
        for (int m = 8; m >= 1; m >>= 1) v += __shfl_xor_sync(0xffffffffu, v, m, 16);
        float inv = rsqrtf(v * 0.0078125f + 1e-5f);
        #pragma unroll
        for (int j = 0; j < 8; ++j) a[i][j] = (a[i][j] - mean) * inv * gv[j] + bv[j];
    }
}

// Full gated MLP on the 64x384 X tile in smem; result (silu(core)*sigmoid(gate))
// left in attn[4][8].
__device__ __forceinline__ void gated_mlp(
    const float* __restrict__ Xsm, float* __restrict__ Hsm, float* __restrict__ Wsm,
    const float* __restrict__ w1c, const float* __restrict__ w2c,
    const float* __restrict__ w1g, const float* __restrict__ w2g,
    const float* __restrict__ lgc, const float* __restrict__ lbc,
    const float* __restrict__ lgg, const float* __restrict__ lbg,
    float attn[4][8], int r0, int c0, int tid)
{
    u64_t acc[4][4];
    float a[4][8];

    // ---- core branch ----
    zero_acc(acc);
    gemm_tile(Xsm, XLD, w1c, Wsm, 384, acc, r0, c0, tid);
    acc_to_f(acc, a);
    __syncthreads();
    #pragma unroll
    for (int i = 0; i < 4; ++i) {
        float4 h0 = {siluf(a[i][0]), siluf(a[i][1]), siluf(a[i][2]), siluf(a[i][3])};
        float4 h1 = {siluf(a[i][4]), siluf(a[i][5]), siluf(a[i][6]), siluf(a[i][7])};
        *(float4*)(Hsm + (r0 + i) * HLD + c0)     = h0;
        *(float4*)(Hsm + (r0 + i) * HLD + c0 + 4) = h1;
    }
    zero_acc(acc);
    gemm_tile(Hsm, HLD, w2c, Wsm, 128, acc, r0, c0, tid);
    acc_to_f(acc, a);
    layernorm_rows(a, lgc, lbc, c0);
    #pragma unroll
    for (int i = 0; i < 4; ++i)
        #pragma unroll
        for (int j = 0; j < 8; ++j) attn[i][j] = a[i][j];   // attn = core (temp)

    // ---- gate branch ----
    zero_acc(acc);
    gemm_tile(Xsm, XLD, w1g, Wsm, 384, acc, r0, c0, tid);
    acc_to_f(acc, a);
    __syncthreads();
    #pragma unroll
    for (int i = 0; i < 4; ++i) {
        float4 h0 = {siluf(a[i][0]), siluf(a[i][1]), siluf(a[i][2]), siluf(a[i][3])};
        float4 h1 = {siluf(a[i][4]), siluf(a[i][5]), siluf(a[i][6]), siluf(a[i][7])};
        *(float4*)(Hsm + (r0 + i) * HLD + c0)     = h0;
        *(float4*)(Hsm + (r0 + i) * HLD + c0 + 4) = h1;
    }
    zero_acc(acc);
    gemm_tile(Hsm, HLD, w2g, Wsm, 128, acc, r0, c0, tid);
    acc_to_f(acc, a);
    layernorm_rows(a, lgg, lbg, c0);
    #pragma unroll
    for (int i = 0; i < 4; ++i)
        #pragma unroll
        for (int j = 0; j < 8; ++j)
            attn[i][j] = siluf(attn[i][j]) * sigmf(a[i][j]);
}

// ---------------------------------------------------------------------------
// prep: zero softmax accumulators, transpose w_src / w_tgt (so z-GEMMs stage
// weights identically to the MLP GEMMs)
// ---------------------------------------------------------------------------
__global__ void prep_kernel(const float* __restrict__ w_src,
                            const float* __restrict__ w_tgt, int nN)
{
    int i = blockIdx.x * blockDim.x + threadIdx.x;
    if (i < D * D) {
        int dd = i / D, k = i % D;
        g_wsrcT[k * D + dd] = w_src[i];
        g_wtgtT[k * D + dd] = w_tgt[i];
    }
    if (i < nN * D) {
        g_num_src[i] = 0.f; g_den_src[i] = 0.f;
        g_num_tgt[i] = 0.f; g_den_tgt[i] = 0.f;
    }
}

// ---------------------------------------------------------------------------
// edge kernel: gather -> gated MLP -> write attn_edge(+residual) -> z GEMMs ->
// exp -> vec4 red atomics into num/den accumulators
// ---------------------------------------------------------------------------
__global__ void __launch_bounds__(NTHREADS) edge_kernel(
    const float* __restrict__ node_feat, const float* __restrict__ edge_feat,
    const float* __restrict__ w1c, const float* __restrict__ w2c,
    const float* __restrict__ w1g, const float* __restrict__ w2g,
    const float* __restrict__ lgc, const float* __restrict__ lbc,
    const float* __restrict__ lgg, const float* __restrict__ lbg,
    const float* __restrict__ edge_res_w,
    const int* __restrict__ src_idx, const int* __restrict__ tgt_idx,
    float* __restrict__ out_edge, int nE)
{
    extern __shared__ float sm[];
    float* Xsm = sm;
    float* Hsm = sm + TILE * XLD;
    float* Wsm = Hsm + TILE * HLD;
    __shared__ int sidx[TILE], tidx[TILE];

    int tid = threadIdx.x;
    int e0 = blockIdx.x * TILE;
    if (tid < TILE) {
        int e = e0 + tid;
        sidx[tid] = (e < nE) ? src_idx[e] : 0;
        tidx[tid] = (e < nE) ? tgt_idx[e] : 0;
    }
    __syncthreads();

    // fill X = [edge_feat | tgt | src], 64 rows x 96 float4
    for (int idx = tid; idx < TILE * 96; idx += NTHREADS) {
        int e = idx / 96, p = idx % 96;
        float4 v = {0.f, 0.f, 0.f, 0.f};
        if (e0 + e < nE) {
            if (p < 32)
                v = *(const float4*)(edge_feat + (size_t)(e0 + e) * D + p * 4);
            else if (p < 64)
                v = *(const float4*)(node_feat + (size_t)tidx[e] * D + (p - 32) * 4);
            else
                v = *(const float4*)(node_feat + (size_t)sidx[e] * D + (p - 64) * 4);
        }
        *(float4*)(Xsm + e * XLD + p * 4) = v;
    }
    // first gemm's leading __syncthreads orders the fill

    int ty = tid >> 4, tx = tid & 15;
    int r0 = ty * 4, c0 = tx * 8;

    float attn[4][8];
    gated_mlp(Xsm, Hsm, Wsm, w1c, w2c, w1g, w2g, lgc, lbc, lgg, lbg,
              attn, r0, c0, tid);

    // write attn_edge + residual
    float4 rw0 = *(const float4*)(edge_res_w + c0);
    float4 rw1 = *(const float4*)(edge_res_w + c0 + 4);
    float rw[8] = {rw0.x, rw0.y, rw0.z, rw0.w, rw1.x, rw1.y, rw1.z, rw1.w};
    #pragma unroll
    for (int i = 0; i < 4; ++i) {
        int e = e0 + r0 + i;
        if (e < nE) {
            const float* ef = Xsm + (r0 + i) * XLD + c0;
            float4 o0 = {attn[i][0] + rw[0]*ef[0], attn[i][1] + rw[1]*ef[1],
                         attn[i][2] + rw[2]*ef[2], attn[i][3] + rw[3]*ef[3]};
            float4 o1 = {attn[i][4] + rw[4]*ef[4], attn[i][5] + rw[5]*ef[5],
                         attn[i][6] + rw[6]*ef[6], attn[i][7] + rw[7]*ef[7]};
            *(float4*)(out_edge + (size_t)e * D + c0)     = o0;
            *(float4*)(out_edge + (size_t)e * D + c0 + 4) = o1;
        }
    }

    u64_t acc[4][4];
    float a[4][8];

    // z_src = edge_feat @ w_src.T  (uses X cols 0..127)
    zero_acc(acc);
    gemm_tile(Xsm, XLD, g_wsrcT, Wsm, 128, acc, r0, c0, tid);
    acc_to_f(acc, a);
    #pragma unroll
    for (int i = 0; i < 4; ++i) {
        int e = e0 + r0 + i;
        if (e < nE) {
            int n = sidx[r0 + i];
            float ev[8];
            #pragma unroll
            for (int j = 0; j < 8; ++j) ev[j] = __expf(a[i][j]);
            float* dp = g_den_src + (size_t)n * D + c0;
            float* np = g_num_src + (size_t)n * D + c0;
            red4(dp,     ev[0], ev[1], ev[2], ev[3]);
            red4(dp + 4, ev[4], ev[5], ev[6], ev[7]);
            red4(np,     ev[0]*attn[i][0], ev[1]*attn[i][1], ev[2]*attn[i][2], ev[3]*attn[i][3]);
            red4(np + 4, ev[4]*attn[i][4], ev[5]*attn[i][5], ev[6]*attn[i][6], ev[7]*attn[i][7]);
        }
    }

    // z_tgt = edge_feat @ w_tgt.T
    zero_acc(acc);
    gemm_tile(Xsm, XLD, g_wtgtT, Wsm, 128, acc, r0, c0, tid);
    acc_to_f(acc, a);
    #pragma unroll
    for (int i = 0; i < 4; ++i) {
        int e = e0 + r0 + i;
        if (e < nE) {
            int n = tidx[r0 + i];
            float ev[8];
            #pragma unroll
            for (int j = 0; j < 8; ++j) ev[j] = __expf(a[i][j]);
            float* dp = g_den_tgt + (size_t)n * D + c0;
            float* np = g_num_tgt + (size_t)n * D + c0;
            red4(dp,     ev[0], ev[1], ev[2], ev[3]);
            red4(dp + 4, ev[4], ev[5], ev[6], ev[7]);
            red4(np,     ev[0]*attn[i][0], ev[1]*attn[i][1], ev[2]*attn[i][2], ev[3]*attn[i][3]);
            red4(np + 4, ev[4]*attn[i][4], ev[5]*attn[i][5], ev[6]*attn[i][6], ev[7]*attn[i][7]);
        }
    }
}

// ---------------------------------------------------------------------------
// node kernel: fusion = [node_feat | num_tgt/(den_tgt+eps) | num_src/(den_src+eps)]
// -> gated MLP -> + node_res_w * node_feat
// ---------------------------------------------------------------------------
__global__ void __launch_bounds__(NTHREADS) node_kernel(
    const float* __restrict__ node_feat,
    const float* __restrict__ w1c, const float* __restrict__ w2c,
    const float* __restrict__ w1g, const float* __restrict__ w2g,
    const float* __restrict__ lgc, const float* __restrict__ lbc,
    const float* __restrict__ lgg, const float* __restrict__ lbg,
    const float* __restrict__ node_res_w,
    float* __restrict__ out_node, int nN)
{
    extern __shared__ float sm[];
    float* Xsm = sm;
    float* Hsm = sm + TILE * XLD;
    float* Wsm = Hsm + TILE * HLD;

    int tid = threadIdx.x;
    int n0 = blockIdx.x * TILE;

    for (int idx = tid; idx < TILE * 96; idx += NTHREADS) {
        int r = idx / 96, p = idx % 96;
        int n = n0 + r;
        float4 v = {0.f, 0.f, 0.f, 0.f};
        if (n < nN) {
            if (p < 32) {
                v = *(const float4*)(node_feat + (size_t)n * D + p * 4);
            } else if (p < 64) {
                int o = (p - 32) * 4;
                float4 nu = *(const float4*)(g_num_tgt + (size_t)n * D + o);
                float4 de = *(const float4*)(g_den_tgt + (size_t)n * D + o);
                v.x = nu.x / (de.x + 1e-16f); v.y = nu.y / (de.y + 1e-16f);
                v.z = nu.z / (de.z + 1e-16f); v.w = nu.w / (de.w + 1e-16f);
            } else {
                int o = (p - 64) * 4;
                float4 nu = *(const float4*)(g_num_src + (size_t)n * D + o);
                float4 de = *(const float4*)(g_den_src + (size_t)n * D + o);
                v.x = nu.x / (de.x + 1e-16f); v.y = nu.y / (de.y + 1e-16f);
                v.z = nu.z / (de.z + 1e-16f); v.w = nu.w / (de.w + 1e-16f);
            }
        }
        *(float4*)(Xsm + r * XLD + p * 4) = v;
    }

    int ty = tid >> 4, tx = tid & 15;
    int r0 = ty * 4, c0 = tx * 8;

    float attn[4][8];
    gated_mlp(Xsm, Hsm, Wsm, w1c, w2c, w1g, w2g, lgc, lbc, lgg, lbg,
              attn, r0, c0, tid);

    float4 rw0 = *(const float4*)(node_res_w + c0);
    float4 rw1 = *(const float4*)(node_res_w + c0 + 4);
    float rw[8] = {rw0.x, rw0.y, rw0.z, rw0.w, rw1.x, rw1.y, rw1.z, rw1.w};
    #pragma unroll
    for (int i = 0; i < 4; ++i) {
        int n = n0 + r0 + i;
        if (n < nN) {
            const float* nf = Xsm + (r0 + i) * XLD + c0;
            float4 o0 = {attn[i][0] + rw[0]*nf[0], attn[i][1] + rw[1]*nf[1],
                         attn[i][2] + rw[2]*nf[2], attn[i][3] + rw[3]*nf[3]};
            float4 o1 = {attn[i][4] + rw[4]*nf[4], attn[i][5] + rw[5]*nf[5],
                         attn[i][6] + rw[6]*nf[6], attn[i][7] + rw[7]*nf[7]};
            *(float4*)(out_node + (size_t)n * D + c0)     = o0;
            *(float4*)(out_node + (size_t)n * D + c0 + 4) = o1;
        }
    }
}

// ---------------------------------------------------------------------------
extern "C" void kernel_launch(void* const* d_in, const int* in_sizes, int n_in,
                              void* d_out, int out_size)
{
    const float* node_feat = (const float*)d_in[0];
    const float* edge_feat = (const float*)d_in[1];
    const float* w_src     = (const float*)d_in[2];
    const float* w_tgt     = (const float*)d_in[3];
    const float* e_core_w1 = (const float*)d_in[4];
    const float* e_core_w2 = (const float*)d_in[5];
    const float* e_gate_w1 = (const float*)d_in[6];
    const float* e_gate_w2 = (const float*)d_in[7];
    const float* e_ln_cg   = (const float*)d_in[8];
    const float* e_ln_cb   = (const float*)d_in[9];
    const float* e_ln_gg   = (const float*)d_in[10];
    const float* e_ln_gb   = (const float*)d_in[11];
    const float* n_core_w1 = (const float*)d_in[12];
    const float* n_core_w2 = (const float*)d_in[13];
    const float* n_gate_w1 = (const float*)d_in[14];
    const float* n_gate_w2 = (const float*)d_in[15];
    const float* n_ln_cg   = (const float*)d_in[16];
    const float* n_ln_cb   = (const float*)d_in[17];
    const float* n_ln_gg   = (const float*)d_in[18];
    const float* n_ln_gb   = (const float*)d_in[19];
    const float* node_res_w= (const float*)d_in[20];
    const float* edge_res_w= (const float*)d_in[21];
    const int*   src_idx   = (const int*)d_in[22];
    const int*   tgt_idx   = (const int*)d_in[23];

    int nN = in_sizes[0] / D;
    int nE = in_sizes[1] / D;

    float* out_node = (float*)d_out;
    float* out_edge = out_node + (size_t)nN * D;

    cudaFuncSetAttribute(edge_kernel, cudaFuncAttributeMaxDynamicSharedMemorySize, SMEM_BYTES);
    cudaFuncSetAttribute(node_kernel, cudaFuncAttributeMaxDynamicSharedMemorySize, SMEM_BYTES);

    prep_kernel<<<(nN * D + 255) / 256, 256>>>(w_src, w_tgt, nN);

    edge_kernel<<<(nE + TILE - 1) / TILE, NTHREADS, SMEM_BYTES>>>(
        node_feat, edge_feat,
        e_core_w1, e_core_w2, e_gate_w1, e_gate_w2,
        e_ln_cg, e_ln_cb, e_ln_gg, e_ln_gb,
        edge_res_w, src_idx, tgt_idx, out_edge, nE);

    node_kernel<<<(nN + TILE - 1) / TILE, NTHREADS, SMEM_BYTES>>>(
        node_feat,
        n_core_w1, n_core_w2, n_gate_w1, n_gate_w2,
        n_ln_cg, n_ln_cb, n_ln_gg, n_ln_gb,
        node_res_w, out_node, nN);
}